// round 17
// baseline (speedup 1.0000x reference)
#include <cuda_runtime.h>
#include <cuda_fp16.h>
#include <cstdint>

#define LL 32768
#define HH 256
#define NS 512
#define CT 128    // scan chunk length (round-13 proven)
#define NC 256
#define NSEG 16   // scan segments (16 chunks each)

// ---------------- device scratch ---------------------------------------------
__device__ __half g_bur[(size_t)LL * NS];      // Bu real fp16
__device__ __half g_bui[(size_t)LL * NS];      // Bu imag fp16
__device__ __half g_sh[(size_t)LL * 2 * NS];   // states fp16 [L][1024] (re|im)
__device__ __half g_uh[(size_t)LL * HH];       // U fp16
__device__ __half g_bc[2 * NS * HH];           // reordered gamma-B fp16 (single)
__device__ __half g_cchi[HH * 2 * NS];         // [256][1024]: Cre | -Cim hi
__device__ __half g_cclo[HH * 2 * NS];
__device__ float2 g_chunk[NC * NS];
__device__ float2 g_seg[NSEG * NS];
__device__ float2 g_segpref[NSEG * NS];
__device__ float2 g_lam[NS];
__device__ float2 g_lamT[NS];                  // lambda^CT = lambda^128
__device__ float  g_gamma[NS];

// ---------------- helpers ----------------------------------------------------
__device__ __forceinline__ float2 cmul(float2 a, float2 b) {
    return make_float2(a.x * b.x - a.y * b.y, a.x * b.y + a.y * b.x);
}
__device__ __forceinline__ void h16_split(float x, __half& hi, __half& lo) {
    hi = __float2half_rn(x);
    lo = __float2half_rn(x - __half2float(hi));
}
__device__ __forceinline__ uint32_t smem_u32(const void* p) {
    return (uint32_t)__cvta_generic_to_shared(p);
}
__device__ __forceinline__ void cpa16(const void* dst_smem, const void* src) {
    asm volatile("cp.async.cg.shared.global [%0], [%1], 16;"
                 :: "r"(smem_u32(dst_smem)), "l"(src));
}
#define CPA_COMMIT asm volatile("cp.async.commit_group;")

__device__ __forceinline__ void mma16(float* c, const uint32_t* a, const uint32_t* b) {
    asm volatile(
        "mma.sync.aligned.m16n8k16.row.col.f32.f16.f16.f32 "
        "{%0,%1,%2,%3},{%4,%5,%6,%7},{%8,%9},{%0,%1,%2,%3};"
        : "+f"(c[0]), "+f"(c[1]), "+f"(c[2]), "+f"(c[3])
        : "r"(a[0]), "r"(a[1]), "r"(a[2]), "r"(a[3]), "r"(b[0]), "r"(b[1]));
}
__device__ __forceinline__ void ldm_x4(uint32_t* r, uint32_t addr) {
    asm volatile("ldmatrix.sync.aligned.m8n8.x4.shared.b16 {%0,%1,%2,%3}, [%4];"
                 : "=r"(r[0]), "=r"(r[1]), "=r"(r[2]), "=r"(r[3]) : "r"(addr));
}

// ---------------- setup kernels ----------------------------------------------
__global__ void k_setup(const float* __restrict__ nu_log,
                        const float* __restrict__ theta_log) {
    int n = threadIdx.x;
    if (n >= NS) return;
    float nu    = expf(nu_log[n]);
    float theta = expf(theta_log[n]);
    float mag   = expf(-nu);
    float2 lam  = make_float2(mag * cosf(theta), mag * sinf(theta));
    g_lam[n]   = lam;
    g_gamma[n] = sqrtf(fmaxf(1.0f - mag * mag, 0.0f));
    float2 t = lam;
    #pragma unroll
    for (int i = 0; i < 7; i++) t = cmul(t, t);   // lambda^128
    g_lamT[n] = t;
}

// fused prep: U->fp16 (blocks [0,8192)), gamma-B (blocks [8192,8704)),
// C concat (blocks [8704,9216)). Runs after k_setup (needs g_gamma).
__global__ void k_prep(const float* __restrict__ U,
                       const float* __restrict__ Bre, const float* __restrict__ Bim,
                       const float* __restrict__ Cre, const float* __restrict__ Cim) {
    int b = blockIdx.x;
    if (b < 8192) {
        size_t i = ((size_t)b * 256 + threadIdx.x) * 4;
        float4 v = *(const float4*)&U[i];
        *(__half2*)&g_uh[i]     = __halves2half2(__float2half_rn(v.x), __float2half_rn(v.y));
        *(__half2*)&g_uh[i + 2] = __halves2half2(__float2half_rn(v.z), __float2half_rn(v.w));
    } else if (b < 8704) {
        int i = (b - 8192) * 256 + threadIdx.x;   // < NS*HH
        int n = i / HH, h = i % HH;
        float gam = g_gamma[n];
        int grp = n >> 5, j = n & 31;
        g_bc[(size_t)(grp * 64 + j) * HH + h]      = __float2half_rn(Bre[i] * gam);
        g_bc[(size_t)(grp * 64 + 32 + j) * HH + h] = __float2half_rn(Bim[i] * gam);
    } else {
        int i = (b - 8704) * 256 + threadIdx.x;   // < HH*NS
        int h = i / NS, n = i % NS;
        __half hi, lo;
        h16_split(Cre[i], hi, lo);
        g_cchi[(size_t)h * (2*NS) + n] = hi;  g_cclo[(size_t)h * (2*NS) + n] = lo;
        h16_split(-Cim[i], hi, lo);
        g_cchi[(size_t)h * (2*NS) + NS + n] = hi;  g_cclo[(size_t)h * (2*NS) + NS + n] = lo;
    }
}

// ---------------- GEMM machinery: BK=64 stages --------------------------------
// Block 128(M) x 64(N) x 64(K); 256 thr = 8 warps (4M x 2N); warp 32x32.
// gemm1: B single pass (4 stages). gemm2: B hi+lo (16 stages).
// Row = 64 halfs + 8 pad = 144B (bank-conflict-free for ldmatrix: 4r mod 32).
static constexpr int ROWB    = 144;
static constexpr int A_BYTES = 128 * ROWB;             // 18432
static constexpr int B_BYTES = 64 * ROWB;              // 9216
static constexpr int STG1    = A_BYTES + B_BYTES;      // 27648
static constexpr int STG2    = A_BYTES + 2 * B_BYTES;  // 36864
static constexpr int SMEM1   = 2 * STG1;               // 55296 (> ep 34816)
static constexpr int SMEM2   = 2 * STG2;               // 73728

template<bool LO>
__device__ __forceinline__ void load_stage(char* stg, const __half* gA, int lda,
                                           const __half* gBh, const __half* gBl,
                                           int ldb, int k0, int t) {
    __half* A  = (__half*)stg;
    __half* Bh = (__half*)(stg + A_BYTES);
    __half* Bl = (__half*)(stg + A_BYTES + B_BYTES);
    #pragma unroll
    for (int i = 0; i < 4; i++) {                  // A: 128 rows x 8 x 16B
        int idx = t + i * 256;
        int r = idx >> 3, c = idx & 7;
        cpa16(&A[r * 72 + c * 8], gA + (size_t)r * lda + k0 + c * 8);
    }
    #pragma unroll
    for (int i = 0; i < 2; i++) {                  // B: 64 rows x 8 x 16B
        int idx = t + i * 256;
        int r = idx >> 3, c = idx & 7;
        cpa16(&Bh[r * 72 + c * 8], gBh + (size_t)r * ldb + k0 + c * 8);
        if (LO) cpa16(&Bl[r * 72 + c * 8], gBl + (size_t)r * ldb + k0 + c * 8);
    }
}

__device__ __forceinline__ void mk_offsets(int wm, int wn, int lane,
                                           uint32_t* oA, uint32_t* oB) {
    #pragma unroll
    for (int mi = 0; mi < 2; mi++) {
        int row = wm * 32 + mi * 16 + (lane & 15);
        oA[mi] = (uint32_t)(row * ROWB + (8 * (lane >> 4)) * 2);
    }
    #pragma unroll
    for (int p = 0; p < 2; p++) {
        int row = wn * 32 + p * 16 + ((lane >> 4) << 3) + (lane & 7);
        oB[p] = (uint32_t)(A_BYTES + row * ROWB + (8 * ((lane >> 3) & 1)) * 2);
    }
}

template<bool LO>
__device__ __forceinline__ void compute_stage(uint32_t sb,
                                              const uint32_t* oA, const uint32_t* oB,
                                              float acc[2][4][4]) {
    #pragma unroll
    for (int kk = 0; kk < 4; kk++) {               // 4 k-steps of 16
        uint32_t af[2][4], bh[2][4], bl[2][4];
        ldm_x4(af[0], sb + oA[0] + kk * 32);
        ldm_x4(af[1], sb + oA[1] + kk * 32);
        ldm_x4(bh[0], sb + oB[0] + kk * 32);
        ldm_x4(bh[1], sb + oB[1] + kk * 32);
        if (LO) {
            ldm_x4(bl[0], sb + oB[0] + B_BYTES + kk * 32);
            ldm_x4(bl[1], sb + oB[1] + B_BYTES + kk * 32);
        }
        #pragma unroll
        for (int mi = 0; mi < 2; mi++)
            #pragma unroll
            for (int p = 0; p < 2; p++) {
                mma16(acc[mi][2*p],     af[mi], &bh[p][0]);
                mma16(acc[mi][2*p + 1], af[mi], &bh[p][2]);
                if (LO) {
                    mma16(acc[mi][2*p],     af[mi], &bl[p][0]);
                    mma16(acc[mi][2*p + 1], af[mi], &bl[p][2]);
                }
            }
    }
}

// 2-stage ring, 1 sync per BK=64 stage
#define GEMM_RING(KT, GA, LDA_, GBH, GBL, STG, LO)                               \
    load_stage<LO>(dynsm, GA, LDA_, GBH, GBL, LDA_, 0, t);  CPA_COMMIT;          \
    for (int it = 0; it < (KT); it++) {                                          \
        asm volatile("cp.async.wait_group 0;");                                  \
        __syncthreads();                                                         \
        if (it + 1 < (KT)) {                                                     \
            load_stage<LO>(dynsm + ((it + 1) & 1) * (STG), GA, LDA_, GBH, GBL,   \
                           LDA_, (it + 1) * 64, t);                              \
            CPA_COMMIT;                                                          \
        }                                                                        \
        compute_stage<LO>(sb0 + ((it) & 1) * (STG), oA, oB, acc);                \
    }

// ---------------- GEMM1 + fused chunk reduce ---------------------------------
// grid (16, 256): x = state-group (32 n's, 64 bcat rows), y = chunk (128 L-rows)
__global__ __launch_bounds__(256, 4) void k_gemm1() {
    extern __shared__ char dynsm[];
    __shared__ float2 seg[4][32];
    int t = threadIdx.x;
    int w = t >> 5, lane = t & 31, g = lane >> 2, t4 = lane & 3;
    int wm = w >> 1, wn = w & 1;
    int row0 = blockIdx.y * 128;
    int n0 = blockIdx.x * 32;
    uint32_t sb0 = smem_u32(dynsm);

    uint32_t oA[2], oB[2];
    mk_offsets(wm, wn, lane, oA, oB);

    const __half* gA = g_uh + (size_t)row0 * HH;
    const __half* gB = g_bc + (size_t)(blockIdx.x * 64) * HH;

    float acc[2][4][4] = {};
    GEMM_RING(HH / 64, gA, HH, gB, (const __half*)nullptr, STG1, false);
    __syncthreads();

    float (*ep)[68] = (float(*)[68])dynsm;
    #pragma unroll
    for (int mi = 0; mi < 2; mi++) {
        int r0 = wm * 32 + mi * 16 + g;
        #pragma unroll
        for (int ni = 0; ni < 4; ni++) {
            int c = wn * 32 + ni * 8 + 2 * t4;
            *(float2*)&ep[r0][c]     = make_float2(acc[mi][ni][0], acc[mi][ni][1]);
            *(float2*)&ep[r0 + 8][c] = make_float2(acc[mi][ni][2], acc[mi][ni][3]);
        }
    }
    __syncthreads();

    // coalesced fp16 write of Bu
    #pragma unroll
    for (int i = 0; i < 16; i++) {
        int fi = t + i * 256;
        int r = fi >> 5, p = fi & 31;
        if (p < 16) {
            __half2 v = __halves2half2(__float2half_rn(ep[r][2*p]),
                                       __float2half_rn(ep[r][2*p + 1]));
            *(__half2*)&g_bur[(size_t)(row0 + r) * NS + n0 + 2*p] = v;
        } else {
            int q = p - 16;
            __half2 v = __halves2half2(__float2half_rn(ep[r][32 + 2*q]),
                                       __float2half_rn(ep[r][32 + 2*q + 1]));
            *(__half2*)&g_bui[(size_t)(row0 + r) * NS + n0 + 2*q] = v;
        }
    }

    // fused chunk Horner: 4 warps x 32-row segments + lambda^32 combine
    if (w < 4) {
        float2 lam = g_lam[n0 + lane];
        float2 b = make_float2(0.f, 0.f);
        int rbase = w * 32;
        #pragma unroll 4
        for (int r = 0; r < 32; r++) {
            float2 tt = cmul(lam, b);
            b = make_float2(tt.x + ep[rbase + r][lane],
                            tt.y + ep[rbase + r][32 + lane]);
        }
        seg[w][lane] = b;
    }
    __syncthreads();
    if (w == 0) {
        float2 lam = g_lam[n0 + lane];
        float2 l32 = lam;
        #pragma unroll
        for (int i = 0; i < 5; i++) l32 = cmul(l32, l32);
        float2 b = seg[0][lane];
        #pragma unroll
        for (int s = 1; s < 4; s++) {
            float2 tt = cmul(l32, b);
            b = make_float2(tt.x + seg[s][lane].x, tt.y + seg[s][lane].y);
        }
        g_chunk[blockIdx.y * NS + n0 + lane] = b;
    }
}

// ---------------- two-level cross-chunk scan (16 seg x 16) --------------------
__global__ __launch_bounds__(512) void k_scan1() {
    int s = blockIdx.x, n = threadIdx.x;
    float2 lamT = g_lamT[n];
    float2 v[16];
    #pragma unroll
    for (int j = 0; j < 16; j++) v[j] = g_chunk[(s * 16 + j) * NS + n];
    float2 b = make_float2(0.f, 0.f);
    #pragma unroll
    for (int j = 0; j < 16; j++) {
        float2 tt = cmul(lamT, b);
        b = make_float2(tt.x + v[j].x, tt.y + v[j].y);
    }
    g_seg[s * NS + n] = b;
}

__global__ __launch_bounds__(512) void k_scan2() {
    int n = threadIdx.x;
    float2 lamT = g_lamT[n];
    float2 l16 = lamT;
    #pragma unroll
    for (int i = 0; i < 4; i++) l16 = cmul(l16, l16);   // lambda^2048
    float2 v[16];
    #pragma unroll
    for (int s = 0; s < NSEG; s++) v[s] = g_seg[s * NS + n];
    float2 p = make_float2(0.f, 0.f);
    #pragma unroll
    for (int s = 0; s < NSEG; s++) {
        g_segpref[s * NS + n] = p;
        float2 tt = cmul(l16, p);
        p = make_float2(tt.x + v[s].x, tt.y + v[s].y);
    }
}

// ---------------- apply: segpref + intra-segment walk, batch-8 MLP ------------
__global__ __launch_bounds__(512) void k_apply() {
    int c = blockIdx.x;
    int n = threadIdx.x;
    int s = c >> 4, jrem = c & 15;
    float2 lam  = g_lam[n];
    float2 lamT = g_lamT[n];

    float2 carry = g_segpref[s * NS + n];
    for (int j = 0; j < jrem; j++) {
        float2 b = g_chunk[(s * 16 + j) * NS + n];
        float2 tt = cmul(lamT, carry);
        carry = make_float2(tt.x + b.x, tt.y + b.y);
    }

    size_t base = (size_t)c * CT * NS + n;
    for (int j0 = 0; j0 < CT; j0 += 8) {
        float vr[8], vi[8];
        #pragma unroll
        for (int k = 0; k < 8; k++) {
            size_t idx = base + (size_t)(j0 + k) * NS;
            vr[k] = __half2float(g_bur[idx]);
            vi[k] = __half2float(g_bui[idx]);
        }
        #pragma unroll
        for (int k = 0; k < 8; k++) {
            float2 tt = cmul(lam, carry);
            carry = make_float2(tt.x + vr[k], tt.y + vi[k]);
            size_t l = (size_t)c * CT + j0 + k;
            g_sh[l * (2*NS) + n]      = __float2half_rn(carry.x);
            g_sh[l * (2*NS) + NS + n] = __float2half_rn(carry.y);
        }
    }
}

// ---------------- GEMM2: Y = S @ cc^T + D*U (C hi+lo 2-pass) ------------------
// grid (4, 256): x = h-tile(64), y = L-tile(128). K = 1024, 16 stages.
__global__ __launch_bounds__(256, 3) void k_gemm2(const float* __restrict__ U,
                                                  const float* __restrict__ Dg,
                                                  float* __restrict__ Y) {
    extern __shared__ char dynsm[];
    int t = threadIdx.x;
    int w = t >> 5, lane = t & 31, g = lane >> 2, t4 = lane & 3;
    int wm = w >> 1, wn = w & 1;
    int row0 = blockIdx.y * 128;
    int col0 = blockIdx.x * 64;
    uint32_t sb0 = smem_u32(dynsm);

    uint32_t oA[2], oB[2];
    mk_offsets(wm, wn, lane, oA, oB);

    const int LDA = 2 * NS;
    const __half* gA  = g_sh   + (size_t)row0 * LDA;
    const __half* gBh = g_cchi + (size_t)col0 * LDA;
    const __half* gBl = g_cclo + (size_t)col0 * LDA;

    float acc[2][4][4] = {};
    GEMM_RING((2 * NS) / 64, gA, LDA, gBh, gBl, STG2, true);

    #pragma unroll
    for (int mi = 0; mi < 2; mi++) {
        int l0 = row0 + wm * 32 + mi * 16 + g;
        #pragma unroll
        for (int ni = 0; ni < 4; ni++) {
            int h = col0 + wn * 32 + ni * 8 + 2 * t4;
            float2 d2 = *(const float2*)&Dg[h];
            float2 u0 = *(const float2*)&U[(size_t)l0 * HH + h];
            float2 u1 = *(const float2*)&U[(size_t)(l0 + 8) * HH + h];
            *(float2*)&Y[(size_t)l0 * HH + h] =
                make_float2(acc[mi][ni][0] + d2.x * u0.x, acc[mi][ni][1] + d2.y * u0.y);
            *(float2*)&Y[(size_t)(l0 + 8) * HH + h] =
                make_float2(acc[mi][ni][2] + d2.x * u1.x, acc[mi][ni][3] + d2.y * u1.y);
        }
    }
}

// ---------------- launch ----------------------------------------------------
extern "C" void kernel_launch(void* const* d_in, const int* in_sizes, int n_in,
                              void* d_out, int out_size) {
    const float* U        = (const float*)d_in[0];
    const float* nu_log   = (const float*)d_in[1];
    const float* theta_lg = (const float*)d_in[2];
    const float* Bre      = (const float*)d_in[3];
    const float* Bim      = (const float*)d_in[4];
    const float* Cre      = (const float*)d_in[5];
    const float* Cim      = (const float*)d_in[6];
    const float* D        = (const float*)d_in[7];
    float* Y = (float*)d_out;

    cudaFuncSetAttribute(k_gemm1, cudaFuncAttributeMaxDynamicSharedMemorySize, SMEM1);
    cudaFuncSetAttribute(k_gemm2, cudaFuncAttributeMaxDynamicSharedMemorySize, SMEM2);

    k_setup<<<1, 512>>>(nu_log, theta_lg);
    k_prep<<<9216, 256>>>(U, Bre, Bim, Cre, Cim);
    k_gemm1<<<dim3(16, 256), 256, SMEM1>>>();
    k_scan1<<<NSEG, 512>>>();
    k_scan2<<<1, 512>>>();
    k_apply<<<NC, 512>>>();
    k_gemm2<<<dim3(4, 256), 256, SMEM2>>>(U, D, Y);
}